// round 6
// baseline (speedup 1.0000x reference)
#include <cuda_runtime.h>
#include <cuda_bf16.h>

// StandardDeviationPooling: 4x4 window, stride 2, VALID.
// Input:  [64, 1024, 1024, 1] fp32   Output: [64, 511*511] fp32
// std = sqrt(max(E[x^2] - E[x]^2, 0)) per window.
//
// R6: R5's shuffle-deduped loads (each thread loads exactly ONE float4 per
// input row, warp = 512B contiguous, zero overlap/predication) + warp-boundary
// pair-sums exchanged through a tiny double-buffered smem slot instead of
// lane-31 edge loads. This drops register pressure so __launch_bounds__(256,8)
// holds 32 regs -> full 2048-thread/SM occupancy for DRAM latency hiding.

#define H_IN 1024
#define W_IN 1024
#define H_OUT 511
#define W_OUT 511
#define ROWS_PER_THREAD 8

__global__ __launch_bounds__(256, 8)
void std_pool_kernel(const float* __restrict__ in, float* __restrict__ out) {
    __shared__ float2 xch[2][8];   // [j parity][warp] : lane0's (own01, oq01)

    const int c      = threadIdx.x;          // col-pair index 0..255
    const int lane   = c & 31;
    const int warpid = c >> 5;               // 0..7
    const int r0     = blockIdx.y * ROWS_PER_THREAD;
    const int b      = blockIdx.z;

    const float* __restrict__ inb  = in  + (size_t)b * H_IN * W_IN;
    float* __restrict__       outb = out + (size_t)b * H_OUT * W_OUT;

    const int  ic     = 4 * c;               // own float4: cols 4c..4c+3
    const int  oc0    = 2 * c;
    const int  nwarp  = (warpid < 7) ? warpid + 1 : 7;  // clamped (w7 lane31 unused)
    const float inv_n = 1.0f / 16.0f;

    // previous row-pair sums/sumsq for the 2 output cols
    float ps0 = 0.f, ps1 = 0.f, pq0 = 0.f, pq1 = 0.f;

    #pragma unroll
    for (int j = 0; j <= ROWS_PER_THREAD; ++j) {
        const int irow = 2 * (r0 + j);

        // own row-pair partials: cols (4c,4c+1) and (4c+2,4c+3)
        float own01 = 0.f, own23 = 0.f, oq01 = 0.f, oq23 = 0.f;

        if (irow + 1 < H_IN) {               // block-uniform guard
            const float* rowp = inb + (size_t)irow * W_IN + ic;
            const float4 a0 = *reinterpret_cast<const float4*>(rowp);
            const float4 a1 = *reinterpret_cast<const float4*>(rowp + W_IN);

            own01 = (a0.x + a0.y) + (a1.x + a1.y);
            own23 = (a0.z + a0.w) + (a1.z + a1.w);
            oq01  = fmaf(a0.x, a0.x, fmaf(a0.y, a0.y,
                    fmaf(a1.x, a1.x, a1.y * a1.y)));
            oq23  = fmaf(a0.z, a0.z, fmaf(a0.w, a0.w,
                    fmaf(a1.z, a1.z, a1.w * a1.w)));
        }

        // publish lane0's left pair to the previous warp's lane 31
        if (lane == 0) xch[j & 1][warpid] = make_float2(own01, oq01);
        __syncthreads();

        // neighbor's (4c+4,4c+5) row-pair partials from lane+1 (or next warp's lane0)
        float n01  = __shfl_down_sync(0xffffffffu, own01, 1);
        float nq01 = __shfl_down_sync(0xffffffffu, oq01, 1);
        if (lane == 31) {
            const float2 t = xch[j & 1][nwarp];
            n01 = t.x; nq01 = t.y;
        }

        const float cs0 = own01 + own23;
        const float cs1 = own23 + n01;
        const float cq0 = oq01 + oq23;
        const float cq1 = oq23 + nq01;

        if (j > 0) {
            const int orow = r0 + j - 1;
            if (orow < H_OUT) {
                float* orow_p = outb + (size_t)orow * W_OUT;
                {
                    const float s = ps0 + cs0, q = pq0 + cq0;
                    const float m = s * inv_n;
                    __stcs(orow_p + oc0, sqrtf(fmaxf(fmaf(-m, m, q * inv_n), 0.f)));
                }
                if (oc0 + 1 < W_OUT) {
                    const float s = ps1 + cs1, q = pq1 + cq1;
                    const float m = s * inv_n;
                    __stcs(orow_p + oc0 + 1, sqrtf(fmaxf(fmaf(-m, m, q * inv_n), 0.f)));
                }
            }
        }
        ps0 = cs0; ps1 = cs1; pq0 = cq0; pq1 = cq1;
    }
}

extern "C" void kernel_launch(void* const* d_in, const int* in_sizes, int n_in,
                              void* d_out, int out_size) {
    const float* in = (const float*)d_in[0];
    float* out = (float*)d_out;
    (void)in_sizes; (void)n_in; (void)out_size;

    // 256 col-pair threads cover 511 output cols; 64 strips of 8 rows; 64 batches.
    dim3 block(256, 1, 1);
    dim3 grid(1, (H_OUT + ROWS_PER_THREAD - 1) / ROWS_PER_THREAD, 64);
    std_pool_kernel<<<grid, block>>>(in, out);
}